// round 9
// baseline (speedup 1.0000x reference)
#include <cuda_runtime.h>
#include <cstdint>

#define T_LEN 2048
#define F_DIM 32
#define B_TOT 512

typedef unsigned long long U;          // packed f32x2 carrier

// ---------------- packed fp32x2 helpers ------------------------------------
__device__ __forceinline__ U ffma2(U a, U b, U c) {
    U d; asm("fma.rn.f32x2 %0, %1, %2, %3;" : "=l"(d) : "l"(a), "l"(b), "l"(c));
    return d;
}
__device__ __forceinline__ U add2(U a, U b) {
    U d; asm("add.rn.f32x2 %0, %1, %2;" : "=l"(d) : "l"(a), "l"(b));
    return d;
}
__device__ __forceinline__ U pack2(float lo, float hi) {
    U d; asm("mov.b64 %0, {%1, %2};" : "=l"(d) : "f"(lo), "f"(hi));
    return d;
}
__device__ __forceinline__ float2 unpk(U d) {
    float2 r; asm("mov.b64 {%0, %1}, %2;" : "=f"(r.x), "=f"(r.y) : "l"(d));
    return r;
}

// ---------------- activations (proven 1.4e-7 end-to-end) --------------------
__device__ __forceinline__ float sig_a(float x) {
    float e = __expf(-x);
    return __fdividef(1.0f, 1.0f + e);
}
__device__ __forceinline__ float tanh_a(float x) {
    x = fminf(15.0f, fmaxf(-15.0f, x));
    float e = __expf(-2.0f * x);
    return __fdividef(1.0f - e, 1.0f + e);
}

// ============================================================================
// Fused LSTM + out-linear.  CTA = 2 batches x (warp A: gates i,f | warp B: g,o)
// -> 4 warps/CTA, one warp per SMSP, 2 CTAs/SM.
// One __syncthreads per step (act exchange, parity buffered).  z single-buffer:
// both warps write identical (h, x) values; own-write + syncwarp gives reuse.
// ============================================================================
__global__ void __launch_bounds__(128, 2)
lstm_fused(const float* __restrict__ x,
           const float* __restrict__ W_ih,
           const float* __restrict__ W_hh,
           const float* __restrict__ b_ih,
           const float* __restrict__ b_hh,
           const float* __restrict__ W_lin,
           const float* __restrict__ b_lin,
           float* __restrict__ out)
{
    __shared__ __align__(16) float  zb[2][2 * F_DIM];       // (h_j,x_j) pairs
    __shared__ __align__(16) float2 ga[2][2][2][F_DIM];     // [lb][par][role] acts
    __shared__ float                pp[2][2][2][F_DIM];     // out partials

    const int tid  = threadIdx.x;
    const int w    = tid >> 5;
    const int f    = tid & 31;
    const int lb   = w >> 1;          // local batch 0/1
    const int role = w & 1;           // 0: gates i,f   1: gates g,o
    const int b    = blockIdx.x * 2 + lb;

    // ---- gate weights: pair j = (W_hh[g,f,j], W_ih[g,f,j]), gates g0,g0+1 ----
    const int g0 = 2 * role;
    U wg0[32], wg1[32];
    {
        const float* ph0 = W_hh + (size_t)(g0 * F_DIM + f) * F_DIM;
        const float* pi0 = W_ih + (size_t)(g0 * F_DIM + f) * F_DIM;
        const float* ph1 = W_hh + (size_t)((g0 + 1) * F_DIM + f) * F_DIM;
        const float* pi1 = W_ih + (size_t)((g0 + 1) * F_DIM + f) * F_DIM;
#pragma unroll
        for (int j = 0; j < 32; j++) {
            wg0[j] = pack2(ph0[j], pi0[j]);
            wg1[j] = pack2(ph1[j], pi1[j]);
        }
    }
    const float bias0 = b_ih[g0 * F_DIM + f] + b_hh[g0 * F_DIM + f];
    const float bias1 = b_ih[(g0 + 1) * F_DIM + f] + b_hh[(g0 + 1) * F_DIM + f];

    // ---- out-linear half: z-pairs 16*role .. 16*role+15 ----
    U wl[16];
    {
        const float* pl = W_lin + (size_t)f * 2 * F_DIM + role * 32;
#pragma unroll
        for (int m = 0; m < 16; m++) wl[m] = pack2(pl[2 * m], pl[2 * m + 1]);
    }
    const float ob = b_lin[f];
    const U ZERO = pack2(0.0f, 0.0f);

    const float* xp = x   + (size_t)b * T_LEN * F_DIM + f;
    float*       op = out + (size_t)b * T_LEN * F_DIM + f;

    float c = 0.0f;
    float prev_y = 0.0f;          // carried x-part of out half
    float xr[4];                  // x ring: slot t&3 holds x_{t+1}

    // ---- preamble: z = (h_{-1}=0, x_0); ring x_1..x_4 (both warps identical) ----
    *(float2*)&zb[lb][2 * f] = make_float2(0.0f, xp[0]);
#pragma unroll
    for (int k = 0; k < 4; k++) xr[k] = xp[(size_t)(k + 1) * F_DIM];
    __syncthreads();

    for (int tb = 0; tb < T_LEN; tb += 2) {
#pragma unroll
        for (int u = 0; u < 2; u++) {
            const int t = tb + u;
            const int s = u;                        // parity buffer

            // ========== phase 1: gate dots + out half over z ==========
            const ulonglong2* zr = (const ulonglong2*)&zb[lb][0];  // 16 x 16B
            U a00 = pack2(bias0, 0.f), a01 = ZERO;
            U a10 = pack2(bias1, 0.f), a11 = ZERO;
#pragma unroll
            for (int q = 0; q < 16; q++) {
                ulonglong2 v = zr[q];
                a00 = ffma2(wg0[2 * q],     v.x, a00);
                a01 = ffma2(wg0[2 * q + 1], v.y, a01);
                a10 = ffma2(wg1[2 * q],     v.x, a10);
                a11 = ffma2(wg1[2 * q + 1], v.y, a11);
            }
            U p0 = ZERO, p1 = ZERO;
#pragma unroll
            for (int m = 0; m < 8; m++) {
                ulonglong2 v = zr[8 * role + m];
                p0 = ffma2(wl[2 * m],     v.x, p0);
                p1 = ffma2(wl[2 * m + 1], v.y, p1);
            }

            float2 s0 = unpk(add2(a00, a01));
            float2 s1 = unpk(add2(a10, a11));
            float pre0 = s0.x + s0.y;
            float pre1 = s1.x + s1.y;
            float act0 = role ? tanh_a(pre0) : sig_a(pre0);  // g : i
            float act1 = sig_a(pre1);                        // o : f

            float2 ps = unpk(add2(p0, p1));
            float part = ps.x + prev_y;        // h(t-1)-part + x(t-1)-part
            prev_y = ps.y;                     // carry x(t)-part

            ga[lb][s][role][f] = make_float2(act0, act1);
            pp[lb][s][role][f] = part;

            __syncthreads();   // the only CTA barrier per step

            // ========== phase 2: redundant c/h, z restage, out finish ==========
            float2 qa = ga[lb][s][0][f];   // (i, f)
            float2 qb = ga[lb][s][1][f];   // (g, o)
            c = qa.y * c + qa.x * qb.x;
            float h = qb.y * tanh_a(c);
            *(float2*)&zb[lb][2 * f] = make_float2(h, xr[t & 3]);  // (h_t, x_{t+1})

            if (role == (t & 1) && t > 0) {
                float sum = pp[lb][s][0][f] + pp[lb][s][1][f] + ob;
                op[(size_t)(t - 1) * F_DIM] = tanh_a(sum);
            }

            int pt = t + 5; if (pt > T_LEN - 1) pt = T_LEN - 1;
            xr[t & 3] = xp[(size_t)pt * F_DIM];

            __syncwarp();      // own z writes visible to own next-step reads
        }
    }

    // ---- epilogue: out_{T-1}.  zb = (h_{T-1}, ...): take .x halves + prev_y ----
    {
        const ulonglong2* zr = (const ulonglong2*)&zb[lb][0];
        U p0 = ZERO, p1 = ZERO;
#pragma unroll
        for (int m = 0; m < 8; m++) {
            ulonglong2 v = zr[8 * role + m];
            p0 = ffma2(wl[2 * m],     v.x, p0);
            p1 = ffma2(wl[2 * m + 1], v.y, p1);
        }
        float2 ps = unpk(add2(p0, p1));
        pp[lb][0][role][f] = ps.x + prev_y;
        __syncthreads();
        if (role == 0) {
            float sum = pp[lb][0][0][f] + pp[lb][0][1][f] + ob;
            op[(size_t)(T_LEN - 1) * F_DIM] = tanh_a(sum);
        }
    }
}

// ============================================================================
extern "C" void kernel_launch(void* const* d_in, const int* in_sizes, int n_in,
                              void* d_out, int out_size)
{
    const float* x     = (const float*)d_in[0];
    const float* W_ih  = (const float*)d_in[1];
    const float* W_hh  = (const float*)d_in[2];
    const float* b_ih  = (const float*)d_in[3];
    const float* b_hh  = (const float*)d_in[4];
    const float* W_lin = (const float*)d_in[5];
    const float* b_lin = (const float*)d_in[6];
    float* out = (float*)d_out;

    lstm_fused<<<B_TOT / 2, 128>>>(x, W_ih, W_hh, b_ih, b_hh, W_lin, b_lin, out);
}

// round 10
// speedup vs baseline: 1.5235x; 1.5235x over previous
#include <cuda_runtime.h>
#include <cstdint>

#define T_LEN 2048
#define F_DIM 32
#define B_TOT 512

typedef unsigned long long U;          // packed f32x2 carrier

// ---------------- packed fp32x2 helpers ------------------------------------
__device__ __forceinline__ U ffma2(U a, U b, U c) {
    U d; asm("fma.rn.f32x2 %0, %1, %2, %3;" : "=l"(d) : "l"(a), "l"(b), "l"(c));
    return d;
}
__device__ __forceinline__ U add2(U a, U b) {
    U d; asm("add.rn.f32x2 %0, %1, %2;" : "=l"(d) : "l"(a), "l"(b));
    return d;
}
__device__ __forceinline__ U pack2(float lo, float hi) {
    U d; asm("mov.b64 %0, {%1, %2};" : "=l"(d) : "f"(lo), "f"(hi));
    return d;
}
__device__ __forceinline__ float2 unpk(U d) {
    float2 r; asm("mov.b64 {%0, %1}, %2;" : "=f"(r.x), "=f"(r.y) : "l"(d));
    return r;
}

// ---------------- fast activations (MUFU.TANH) ------------------------------
__device__ __forceinline__ float tanh_f(float x) {
    float y; asm("tanh.approx.f32 %0, %1;" : "=f"(y) : "f"(x));
    return y;
}
__device__ __forceinline__ float sig_f(float x) {
    return fmaf(tanh_f(0.5f * x), 0.5f, 0.5f);
}
// accurate tanh for the FINAL output only (sits directly on scored values)
__device__ __forceinline__ float tanh_acc(float x) {
    x = fminf(15.0f, fmaxf(-15.0f, x));
    float e = __expf(-2.0f * x);
    return __fdividef(1.0f - e, 1.0f + e);
}

// ============================================================================
// Fused LSTM + out-linear. CTA = 1 batch, 4 warps (warp = gate), 4 CTAs/SM.
// Phase 1 (critical): h-dot only (xacc carried) + act + out-h chunk, BAR1.
// Phase 2 (shadow):  warp3 c/h + staging; ALL warps precompute xacc(t+1) and
//                    out-x chunk(t); warp0 finalizes out_{t-1}. BAR2.
// x ring xb[4]: slot t&3 = x_t; warp3 writes slot (t+2)&3 = x_{t+2} at
// phase2(t); readers touch slots t&3 and (t+1)&3 only -> no conflicts,
// visibility via the two barriers between write and read.
// ============================================================================
__global__ void __launch_bounds__(128, 4)
lstm_fused(const float* __restrict__ x,
           const float* __restrict__ W_ih,
           const float* __restrict__ W_hh,
           const float* __restrict__ b_ih,
           const float* __restrict__ b_hh,
           const float* __restrict__ W_lin,
           const float* __restrict__ b_lin,
           float* __restrict__ out)
{
    __shared__ __align__(16) float  hb[F_DIM];        // h_{t-1}
    __shared__ __align__(16) float  xb[4][F_DIM];     // x ring (slot = t&3)
    __shared__ __align__(16) float2 gp[2][4][F_DIM];  // (act, out_partial), parity

    const int w = threadIdx.x >> 5;    // warp = gate (0:i 1:f 2:g 3:o)
    const int f = threadIdx.x & 31;    // lane = feature
    const int b = blockIdx.x;          // batch

    // ---- gate weights: consecutive-j pairs ----
    U whh[16], wih[16];
    {
        const U* ph = (const U*)(W_hh + (size_t)(w * F_DIM + f) * F_DIM);
        const U* pi = (const U*)(W_ih + (size_t)(w * F_DIM + f) * F_DIM);
#pragma unroll
        for (int k = 0; k < 16; k++) { whh[k] = ph[k]; wih[k] = pi[k]; }
    }
    const float bias = b_ih[w * F_DIM + f] + b_hh[w * F_DIM + f];

    // ---- out-linear chunk: j in [8w, 8w+8) ----
    U wlh[4], wlx[4];
    {
        const float* pl = W_lin + (size_t)f * 2 * F_DIM;
#pragma unroll
        for (int m = 0; m < 4; m++) {
            wlh[m] = pack2(pl[16 * w + 4 * m],     pl[16 * w + 4 * m + 2]);
            wlx[m] = pack2(pl[16 * w + 4 * m + 1], pl[16 * w + 4 * m + 3]);
        }
    }
    const float ob = b_lin[f];
    const U ZERO = pack2(0.0f, 0.0f);

    const float* xp = x   + (size_t)b * T_LEN * F_DIM + f;
    float*       op = out + (size_t)b * T_LEN * F_DIM + f;

    float c = 0.0f;            // warp3: cell state
    float prev_px = 0.0f;      // carried out-x chunk over x_{t-1}
    float xr[4];               // warp3: LDG ring, xr[t&3] = x_{t+2}

    // ---- init: h_{-1}=0, xb[0]=x_0, xb[1]=x_1, xr=x_2..x_5 ----
    if (w == 3) {
        hb[f] = 0.0f;
        xb[0][f] = xp[0];
        xb[1][f] = xp[F_DIM];
#pragma unroll
        for (int k = 0; k < 4; k++) xr[k] = xp[(size_t)(k + 2) * F_DIM];
    }
    __syncthreads();

    // xacc over x_0
    U xacc0, xacc1;
    {
        const ulonglong2* xz = (const ulonglong2*)&xb[0][0];
        xacc0 = pack2(bias, 0.0f); xacc1 = ZERO;
#pragma unroll
        for (int i = 0; i < 8; i++) {
            ulonglong2 v = xz[i];
            xacc0 = ffma2(wih[2 * i],     v.x, xacc0);
            xacc1 = ffma2(wih[2 * i + 1], v.y, xacc1);
        }
    }

    float myact = 0.0f, mypart = 0.0f;

    for (int tb = 0; tb < T_LEN; tb += 4) {
#pragma unroll
        for (int u = 0; u < 4; u++) {
            const int t   = tb + u;
            const int par = t & 1;

            // ========== phase 1 (critical): h-dot + act + out-h ==========
            const ulonglong2* hz = (const ulonglong2*)&hb[0];
            U a0 = xacc0, a1 = xacc1;
#pragma unroll
            for (int i = 0; i < 8; i++) {
                ulonglong2 v = hz[i];
                a0 = ffma2(whh[2 * i],     v.x, a0);
                a1 = ffma2(whh[2 * i + 1], v.y, a1);
            }
            ulonglong2 h0 = hz[2 * w];
            ulonglong2 h1 = hz[2 * w + 1];
            U p0 = ffma2(wlh[0], h0.x, ZERO);
            U p1 = ffma2(wlh[1], h0.y, ZERO);
            p0 = ffma2(wlh[2], h1.x, p0);
            p1 = ffma2(wlh[3], h1.y, p1);

            float2 gs = unpk(add2(a0, a1));
            float pre = gs.x + gs.y;
            float act = (w == 2) ? tanh_f(pre) : sig_f(pre);
            float2 ps = unpk(add2(p0, p1));
            float part = ps.x + ps.y + prev_px;      // full partial of out_{t-1}
            myact = act; mypart = part;
            gp[par][w][f] = make_float2(act, part);

            __syncthreads();   // BAR1

            // ========== phase 2 (shadow) ==========
            if (w == 3) {
                float gi = gp[par][0][f].x;
                float gf = gp[par][1][f].x;
                float gg = gp[par][2][f].x;
                c = gf * c + gi * gg;
                float h = myact * tanh_f(c);
                hb[f] = h;
                xb[(t + 2) & 3][f] = xr[t & 3];       // stage x_{t+2}
                int pt = t + 6; if (pt > T_LEN - 1) pt = T_LEN - 1;
                xr[t & 3] = xp[(size_t)pt * F_DIM];   // refill ring
            } else if (w == 0 && t > 0) {
                float sum = mypart + gp[par][1][f].y + gp[par][2][f].y
                          + gp[par][3][f].y + ob;
                op[(size_t)(t - 1) * F_DIM] = tanh_acc(sum);
            }

            // all warps: xacc(t+1) over xb[(t+1)&3]
            {
                const ulonglong2* xz = (const ulonglong2*)&xb[(t + 1) & 3][0];
                xacc0 = pack2(bias, 0.0f); xacc1 = ZERO;
#pragma unroll
                for (int i = 0; i < 8; i++) {
                    ulonglong2 v = xz[i];
                    xacc0 = ffma2(wih[2 * i],     v.x, xacc0);
                    xacc1 = ffma2(wih[2 * i + 1], v.y, xacc1);
                }
            }
            // all warps: out-x chunk over x_t -> carried to next phase 1
            {
                const ulonglong2* xz0 = (const ulonglong2*)&xb[t & 3][0];
                ulonglong2 x0 = xz0[2 * w];
                ulonglong2 x1 = xz0[2 * w + 1];
                U q0 = ffma2(wlx[0], x0.x, ZERO);
                U q1 = ffma2(wlx[1], x0.y, ZERO);
                q0 = ffma2(wlx[2], x1.x, q0);
                q1 = ffma2(wlx[3], x1.y, q1);
                float2 qs = unpk(add2(q0, q1));
                prev_px = qs.x + qs.y;
            }

            __syncthreads();   // BAR2: hb / xb staged visible
        }
    }

    // ---- epilogue: out_{T-1} = Weven·h_{T-1} + prev_px(x_{T-1}) + b ----
    {
        const ulonglong2* hz = (const ulonglong2*)&hb[0];
        ulonglong2 h0 = hz[2 * w];
        ulonglong2 h1 = hz[2 * w + 1];
        U p0 = ffma2(wlh[0], h0.x, ZERO);
        U p1 = ffma2(wlh[1], h0.y, ZERO);
        p0 = ffma2(wlh[2], h1.x, p0);
        p1 = ffma2(wlh[3], h1.y, p1);
        float2 ps = unpk(add2(p0, p1));
        float part = ps.x + ps.y + prev_px;
        gp[0][w][f] = make_float2(0.0f, part);
        __syncthreads();
        if (w == 0) {
            float sum = gp[0][0][f].y + gp[0][1][f].y + gp[0][2][f].y
                      + gp[0][3][f].y + ob;
            op[(size_t)(T_LEN - 1) * F_DIM] = tanh_acc(sum);
        }
    }
}

// ============================================================================
extern "C" void kernel_launch(void* const* d_in, const int* in_sizes, int n_in,
                              void* d_out, int out_size)
{
    const float* x     = (const float*)d_in[0];
    const float* W_ih  = (const float*)d_in[1];
    const float* W_hh  = (const float*)d_in[2];
    const float* b_ih  = (const float*)d_in[3];
    const float* b_hh  = (const float*)d_in[4];
    const float* W_lin = (const float*)d_in[5];
    const float* b_lin = (const float*)d_in[6];
    float* out = (float*)d_out;

    lstm_fused<<<B_TOT, 128>>>(x, W_ih, W_hh, b_ih, b_hh, W_lin, b_lin, out);
}